// round 14
// baseline (speedup 1.0000x reference)
#include <cuda_runtime.h>
#include <cstdint>

// ============================================================
// BoneLinear: out = x @ (weight + w)^T
// Step 1: Weff = weight + wblk@bone + bone (tf32 RNA) into g_weff
//         R14: epilogue reads weight/bone from SMEM (no gmem re-read);
//              bT pitch 65 -> conflict-free transpose fill + reads.
// Step 2: tf32 mma.sync GEMM [16384,4096] x [4096,4096]^T (frozen, R12)
// ============================================================

#define MDIM 16384
#define NDIM 4096
#define KDIM 4096

#define BM 128
#define BN 128
#define BK 32
#define STAGES 3
#define KT (KDIM / BK)        // 128
#define THREADS 128

// smem: 32 floats (128B) per row padded to 36 floats (144B) -> conflict-free
#define PITCH_F 36
#define PITCH_B (PITCH_F * 4)
#define A_STAGE_BYTES (BM * PITCH_B)   // 18432
#define B_STAGE_BYTES (BN * PITCH_B)   // 18432
#define STAGE_BYTES (A_STAGE_BYTES + B_STAGE_BYTES)  // 36864
#define SMEM_TOTAL (STAGES * STAGE_BYTES)            // 110592 (x2 CTAs = 221184)

__device__ float g_weff[(size_t)NDIM * KDIM];        // 64 MB

// ---------------- helpers ----------------
__device__ __forceinline__ uint32_t smem_u32(const void* p) {
    uint32_t a;
    asm("{ .reg .u64 t; cvta.to.shared.u64 t, %1; cvt.u32.u64 %0, t; }" : "=r"(a) : "l"(p));
    return a;
}
__device__ __forceinline__ void cp16(uint32_t sdst, const float* gsrc) {
    asm volatile("cp.async.cg.shared.global [%0], [%1], 16;" :: "r"(sdst), "l"(gsrc));
}
#define CP_COMMIT() asm volatile("cp.async.commit_group;" ::: "memory")
#define CP_WAIT1()  asm volatile("cp.async.wait_group 1;" ::: "memory")

__device__ __forceinline__ void ldmatrix4(uint32_t* r, uint32_t addr) {
    asm volatile("ldmatrix.sync.aligned.m8n8.x4.shared.b16 {%0,%1,%2,%3}, [%4];"
                 : "=r"(r[0]), "=r"(r[1]), "=r"(r[2]), "=r"(r[3]) : "r"(addr));
}
__device__ __forceinline__ uint32_t lds_b32(uint32_t addr) {
    uint32_t v;
    asm volatile("ld.shared.b32 %0, [%1];" : "=r"(v) : "r"(addr));
    return v;
}
__device__ __forceinline__ void mma_tf32(float* c, const uint32_t* a, const uint32_t* b) {
    asm volatile(
        "mma.sync.aligned.m16n8k8.row.col.f32.tf32.tf32.f32 "
        "{%0,%1,%2,%3}, {%4,%5,%6,%7}, {%8,%9}, {%0,%1,%2,%3};"
        : "+f"(c[0]), "+f"(c[1]), "+f"(c[2]), "+f"(c[3])
        : "r"(a[0]), "r"(a[1]), "r"(a[2]), "r"(a[3]), "r"(b[0]), "r"(b[1]));
}

// ---------------- precompute: Weff = weight + wblk@bone + bone, on tensor pipe ----------------
// Block (b, a): wblk[64,64] @ bone[b][64,64] via tf32 mma; epilogue adds
// weight+bone FROM SMEM (wS/bT already hold them).
#define WP 68   // A pitch (words): 16B-aligned for ldmatrix/float4
#define BP 65   // B pitch (words): odd -> bank stride 1, conflict-free both ways
__global__ void __launch_bounds__(128, 6)
bone_weff_kernel(const float* __restrict__ weight, const float* __restrict__ bone,
                 float* __restrict__ weff) {
    __shared__ float wS[64 * WP];   // wS[i*WP + k] = wblk[i][k]    (A, row-major)
    __shared__ float bT[64 * BP];   // bT[j*BP + k] = bone[b][k][j] (B, col-major)
    const int b = blockIdx.x, a = blockIdx.y;
    const int t = threadIdx.x;
    const int wid = t >> 5, lane = t & 31;

    // fill A: coalesced float4 along k
    for (int idx = t; idx < 1024; idx += 128) {
        int i = idx >> 4, k4 = idx & 15;
        float4 v = *reinterpret_cast<const float4*>(
            weight + (size_t)(a * 64 + i) * KDIM + b * 64 + k4 * 4);
        *reinterpret_cast<float4*>(wS + i * WP + k4 * 4) = v;
    }
    // fill B^T: read bone coalesced along j, transpose-store (BP=65 -> conflict-free)
    for (int idx = t; idx < 4096; idx += 128) {
        int k = idx >> 6, j = idx & 63;
        bT[j * BP + k] = bone[(size_t)b * 4096 + k * 64 + j];
    }
    __syncthreads();

    // warp wid handles m-rows wid*16..wid*16+15, all 64 n, k=64 (8 ksteps)
    float c[8][4];
#pragma unroll
    for (int nt = 0; nt < 8; nt++)
#pragma unroll
        for (int q = 0; q < 4; q++) c[nt][q] = 0.0f;

    const uint32_t sbw = smem_u32(wS);
    const uint32_t sbb = smem_u32(bT);
    const uint32_t a_addr = sbw + (uint32_t)(wid * 16 + (lane & 15)) * (WP * 4)
                                + (uint32_t)((lane >> 4) * 16);
    const uint32_t b_row = (uint32_t)(lane >> 2);
    const uint32_t b_koff = (uint32_t)((lane & 3) * 4);

#pragma unroll
    for (int ks = 0; ks < 8; ks++) {
        uint32_t af[4];
        ldmatrix4(af, a_addr + ks * 32);
#pragma unroll
        for (int nt = 0; nt < 8; nt++) {
            uint32_t bfr[2];
            uint32_t ba = sbb + (b_row + nt * 8) * (BP * 4) + (uint32_t)(ks * 32) + b_koff;
            bfr[0] = lds_b32(ba);
            bfr[1] = lds_b32(ba + 16);
            mma_tf32(c[nt], af, bfr);
        }
    }

    // epilogue: weff = cvt.rna(c + weight + bone), operands from SMEM
    //   weight[a*64+i][b*64+j] = wS[i*WP + j]
    //   bone[b][i][j]          = bT[j*BP + i]
    const int er = wid * 16 + (lane >> 2);
    const int ec = 2 * (lane & 3);
#pragma unroll
    for (int nt = 0; nt < 8; nt++) {
#pragma unroll
        for (int h = 0; h < 2; h++) {
            const int i = er + h * 8;
            const int j = ec + nt * 8;
            float r0 = c[nt][h * 2 + 0] + wS[i * WP + j]     + bT[j * BP + i];
            float r1 = c[nt][h * 2 + 1] + wS[i * WP + j + 1] + bT[(j + 1) * BP + i];
            asm("cvt.rna.tf32.f32 %0, %1;" : "=f"(r0) : "f"(r0));
            asm("cvt.rna.tf32.f32 %0, %1;" : "=f"(r1) : "f"(r1));
            *reinterpret_cast<float2*>(
                weff + (size_t)(a * 64 + i) * KDIM + b * 64 + j) = make_float2(r0, r1);
        }
    }
}

// ---------------- main GEMM kernel (frozen from R12) ----------------
__global__ void __launch_bounds__(THREADS, 2)
bone_gemm_kernel(const float* __restrict__ x, const float* __restrict__ weff,
                 float* __restrict__ out) {
    extern __shared__ __align__(128) char smem[];
    const uint32_t sb = smem_u32(smem);

    const int tid = threadIdx.x;
    const int wid = tid >> 5;
    const int lane = tid & 31;
    const int wm = wid & 1;        // 2 warps along M (64 rows each)
    const int wn = wid >> 1;       // 2 warps along N (64 cols each)
    const int bm = blockIdx.y * BM;
    const int bn = blockIdx.x * BN;

    // ---- cp.async: one quarter (2 A chunks + 2 B chunks per thread) ----
    auto issue_part = [&](int kt, int stage, int part) {
        const uint32_t as = sb + stage * STAGE_BYTES;
        const uint32_t bs = as + A_STAGE_BYTES;
        const int kcol = kt * BK;
#pragma unroll
        for (int j = part * 2; j < part * 2 + 2; j++) {
            int idx = tid + j * THREADS;
            int row = idx >> 3, seg = idx & 7;
            cp16(as + row * PITCH_B + seg * 16,
                 x + (size_t)(bm + row) * KDIM + kcol + seg * 4);
            cp16(bs + row * PITCH_B + seg * 16,
                 weff + (size_t)(bn + row) * KDIM + kcol + seg * 4);
        }
    };

    float c[4][8][4];
#pragma unroll
    for (int mt = 0; mt < 4; mt++)
#pragma unroll
        for (int nt = 0; nt < 8; nt++)
#pragma unroll
            for (int q = 0; q < 4; q++) c[mt][nt][q] = 0.0f;

    // per-lane smem offsets
    const uint32_t a_row = (uint32_t)(wm * 64 + (lane & 15));
    const uint32_t a_coff = (uint32_t)((lane >> 4) * 16);          // bytes within k
    const uint32_t b_row = (uint32_t)(wn * 64 + (lane >> 2));      // + nt*8
    const uint32_t b_koff = (uint32_t)((lane & 3) * 4);            // bytes

    // double-buffered fragments
    uint32_t af[2][4][4];
    uint32_t bf[2][8][2];

    auto load_frags = [&](int stage, int ks, int buf) {
        const uint32_t as = sb + stage * STAGE_BYTES;
        const uint32_t bs = as + A_STAGE_BYTES;
        const uint32_t k0b = (uint32_t)(ks * 32);  // 8 floats
#pragma unroll
        for (int mt = 0; mt < 4; mt++)
            ldmatrix4(af[buf][mt], as + (a_row + mt * 16) * PITCH_B + k0b + a_coff);
#pragma unroll
        for (int nt = 0; nt < 8; nt++) {
            uint32_t ba = bs + (b_row + nt * 8) * PITCH_B + k0b + b_koff;
            bf[buf][nt][0] = lds_b32(ba);
            bf[buf][nt][1] = lds_b32(ba + 16);
        }
    };

#define MMAS(B)                                                                    \
    do {                                                                           \
        _Pragma("unroll")                                                          \
        for (int mt = 0; mt < 4; mt++)                                             \
            _Pragma("unroll")                                                      \
            for (int nt = 0; nt < 8; nt++)                                         \
                mma_tf32(c[mt][nt], af[B][mt], bf[B][nt]);                         \
    } while (0)

    // one kt iteration; CS/NS/F2/F3 are compile-time stage constants
#define KT_BODY(KTV, CS, NS, F2, F3)                                               \
    do {                                                                           \
        const int _kt = (KTV);                                                     \
        const bool i23 = _kt + 2 < KT;                                             \
        const bool i3  = _kt + 3 < KT;                                             \
        load_frags(CS, 1, 1);                                                      \
        MMAS(0);                                                                   \
        if (i23) issue_part(_kt + 2, F2, 1);                                       \
        load_frags(CS, 2, 0);                                                      \
        MMAS(1);                                                                   \
        if (i23) issue_part(_kt + 2, F2, 2);                                       \
        load_frags(CS, 3, 1);                                                      \
        MMAS(0);                                                                   \
        if (i23) issue_part(_kt + 2, F2, 3);                                       \
        CP_COMMIT();                                                               \
        CP_WAIT1();                                                                \
        __syncthreads();                                                           \
        if (_kt + 1 < KT) load_frags(NS, 0, 0);                                    \
        MMAS(1);                                                                   \
        if (i3) issue_part(_kt + 3, F3, 0);                                        \
    } while (0)

    // ---- prologue: stage0 full, stage1 full, stage2 part0 ----
#pragma unroll
    for (int p = 0; p < 4; p++) issue_part(0, 0, p);
    CP_COMMIT();
#pragma unroll
    for (int p = 0; p < 4; p++) issue_part(1, 1, p);
    CP_COMMIT();
    issue_part(2, 2, 0);

    CP_WAIT1();          // stage0 group complete
    __syncthreads();
    load_frags(0, 0, 0); // frag0 of kt=0 into buf0

    // ---- mainloop: 42 triples (kt = 0..125), stages compile-time ----
#pragma unroll 1
    for (int kt = 0; kt < 126; kt += 3) {
        KT_BODY(kt,     0, 1, 2, 0);
        KT_BODY(kt + 1, 1, 2, 0, 1);
        KT_BODY(kt + 2, 2, 0, 1, 2);
    }
    // tail: kt = 126 (stage 0), kt = 127 (stage 1)
    KT_BODY(126, 0, 1, 2, 0);
    KT_BODY(127, 1, 2, 0, 1);

#undef KT_BODY
#undef MMAS

    // ---- epilogue: fp32 stores ----
    const int er = bm + wm * 64 + (lane >> 2);
    const int ec = bn + wn * 64 + 2 * (lane & 3);
#pragma unroll
    for (int mt = 0; mt < 4; mt++) {
#pragma unroll
        for (int nt = 0; nt < 8; nt++) {
            float* p0 = out + (size_t)(er + mt * 16) * NDIM + ec + nt * 8;
            float* p1 = p0 + 8 * NDIM;
            *reinterpret_cast<float2*>(p0) = make_float2(c[mt][nt][0], c[mt][nt][1]);
            *reinterpret_cast<float2*>(p1) = make_float2(c[mt][nt][2], c[mt][nt][3]);
        }
    }
}

// ---------------- host ----------------
extern "C" void kernel_launch(void* const* d_in, const int* in_sizes, int n_in,
                              void* d_out, int out_size) {
    (void)in_sizes; (void)n_in; (void)out_size;
    const float* x      = (const float*)d_in[0];
    const float* weight = (const float*)d_in[1];
    const float* bone   = (const float*)d_in[2];
    float* out          = (float*)d_out;

    void* weff_ptr = nullptr;
    cudaGetSymbolAddress(&weff_ptr, g_weff);

    cudaFuncSetAttribute((const void*)bone_gemm_kernel,
                         cudaFuncAttributeMaxDynamicSharedMemorySize, SMEM_TOTAL);

    bone_weff_kernel<<<dim3(64, 64), 128>>>(weight, bone, (float*)weff_ptr);
    bone_gemm_kernel<<<dim3(NDIM / BN, MDIM / BM), THREADS, SMEM_TOTAL>>>(
        x, (const float*)weff_ptr, out);
}

// round 15
// speedup vs baseline: 1.8014x; 1.8014x over previous
#include <cuda_runtime.h>
#include <cuda_fp16.h>
#include <cstdint>

// ============================================================
// BoneLinear: out = x @ (weight + w)^T
// R15: fp16 mma.m16n8k16 GEMM (same 10-bit mantissa as tf32, 2x rate).
//   Step 1a: Weff = weight + wblk@bone + bone  -> fp16 g_weffh (tensor pipe)
//   Step 1b: x -> fp16 g_xh (RN)
//   Step 2:  fp16 GEMM [16384,4096] x [4096,4096]^T, fp32 accum.
// BK=64 halves => byte layout identical to proven tf32/BK=32 kernel.
// ============================================================

#define MDIM 16384
#define NDIM 4096
#define KDIM 4096

#define BM 128
#define BN 128
#define BK 64                 // halves per kt => 128 data bytes per row
#define STAGES 3
#define KT (KDIM / BK)        // 64
#define THREADS 128

// smem: 128-B data rows padded to 144 B (same proven bank layout)
#define PITCH_B 144
#define A_STAGE_BYTES (BM * PITCH_B)   // 18432
#define B_STAGE_BYTES (BN * PITCH_B)   // 18432
#define STAGE_BYTES (A_STAGE_BYTES + B_STAGE_BYTES)  // 36864
#define SMEM_TOTAL (STAGES * STAGE_BYTES)            // 110592 (x2 CTAs = 221184)

__device__ __half g_weffh[(size_t)NDIM * KDIM];      // 32 MB
__device__ __half g_xh[(size_t)MDIM * KDIM];         // 128 MB

// ---------------- helpers ----------------
__device__ __forceinline__ uint32_t smem_u32(const void* p) {
    uint32_t a;
    asm("{ .reg .u64 t; cvta.to.shared.u64 t, %1; cvt.u32.u64 %0, t; }" : "=r"(a) : "l"(p));
    return a;
}
__device__ __forceinline__ void cp16(uint32_t sdst, const void* gsrc) {
    asm volatile("cp.async.cg.shared.global [%0], [%1], 16;" :: "r"(sdst), "l"(gsrc));
}
#define CP_COMMIT() asm volatile("cp.async.commit_group;" ::: "memory")
#define CP_WAIT1()  asm volatile("cp.async.wait_group 1;" ::: "memory")

__device__ __forceinline__ void ldmatrix4(uint32_t* r, uint32_t addr) {
    asm volatile("ldmatrix.sync.aligned.m8n8.x4.shared.b16 {%0,%1,%2,%3}, [%4];"
                 : "=r"(r[0]), "=r"(r[1]), "=r"(r[2]), "=r"(r[3]) : "r"(addr));
}
__device__ __forceinline__ uint32_t lds_b32(uint32_t addr) {
    uint32_t v;
    asm volatile("ld.shared.b32 %0, [%1];" : "=r"(v) : "r"(addr));
    return v;
}
// tf32 mma (used by weff precompute only)
__device__ __forceinline__ void mma_tf32(float* c, const uint32_t* a, const uint32_t* b) {
    asm volatile(
        "mma.sync.aligned.m16n8k8.row.col.f32.tf32.tf32.f32 "
        "{%0,%1,%2,%3}, {%4,%5,%6,%7}, {%8,%9}, {%0,%1,%2,%3};"
        : "+f"(c[0]), "+f"(c[1]), "+f"(c[2]), "+f"(c[3])
        : "r"(a[0]), "r"(a[1]), "r"(a[2]), "r"(a[3]), "r"(b[0]), "r"(b[1]));
}
// fp16 mma, fp32 accum (main GEMM)
__device__ __forceinline__ void mma_f16(float* c, const uint32_t* a, const uint32_t* b) {
    asm volatile(
        "mma.sync.aligned.m16n8k16.row.col.f32.f16.f16.f32 "
        "{%0,%1,%2,%3}, {%4,%5,%6,%7}, {%8,%9}, {%0,%1,%2,%3};"
        : "+f"(c[0]), "+f"(c[1]), "+f"(c[2]), "+f"(c[3])
        : "r"(a[0]), "r"(a[1]), "r"(a[2]), "r"(a[3]), "r"(b[0]), "r"(b[1]));
}

// ---------------- precompute 1a: Weffh = fp16(weight + wblk@bone + bone) ----------------
#define WP 68   // A pitch (words): 16B-aligned for ldmatrix/float4
#define BP 65   // B pitch (words): odd -> conflict-free transpose fill + reads
__global__ void __launch_bounds__(128, 6)
bone_weff_kernel(const float* __restrict__ weight, const float* __restrict__ bone,
                 __half* __restrict__ weffh) {
    __shared__ float wS[64 * WP];   // wS[i*WP + k] = wblk[i][k]
    __shared__ float bT[64 * BP];   // bT[j*BP + k] = bone[b][k][j]
    const int b = blockIdx.x, a = blockIdx.y;
    const int t = threadIdx.x;
    const int wid = t >> 5, lane = t & 31;

    for (int idx = t; idx < 1024; idx += 128) {
        int i = idx >> 4, k4 = idx & 15;
        float4 v = *reinterpret_cast<const float4*>(
            weight + (size_t)(a * 64 + i) * KDIM + b * 64 + k4 * 4);
        *reinterpret_cast<float4*>(wS + i * WP + k4 * 4) = v;
    }
    for (int idx = t; idx < 4096; idx += 128) {
        int k = idx >> 6, j = idx & 63;
        bT[j * BP + k] = bone[(size_t)b * 4096 + k * 64 + j];
    }
    __syncthreads();

    float c[8][4];
#pragma unroll
    for (int nt = 0; nt < 8; nt++)
#pragma unroll
        for (int q = 0; q < 4; q++) c[nt][q] = 0.0f;

    const uint32_t sbw = smem_u32(wS);
    const uint32_t sbb = smem_u32(bT);
    const uint32_t a_addr = sbw + (uint32_t)(wid * 16 + (lane & 15)) * (WP * 4)
                                + (uint32_t)((lane >> 4) * 16);
    const uint32_t b_row = (uint32_t)(lane >> 2);
    const uint32_t b_koff = (uint32_t)((lane & 3) * 4);

#pragma unroll
    for (int ks = 0; ks < 8; ks++) {
        uint32_t af[4];
        ldmatrix4(af, a_addr + ks * 32);
#pragma unroll
        for (int nt = 0; nt < 8; nt++) {
            uint32_t bfr[2];
            uint32_t ba = sbb + (b_row + nt * 8) * (BP * 4) + (uint32_t)(ks * 32) + b_koff;
            bfr[0] = lds_b32(ba);
            bfr[1] = lds_b32(ba + 16);
            mma_tf32(c[nt], af, bfr);
        }
    }

    // epilogue: weffh = fp16_rn(c + weight + bone), operands from SMEM
    const int er = wid * 16 + (lane >> 2);
    const int ec = 2 * (lane & 3);
#pragma unroll
    for (int nt = 0; nt < 8; nt++) {
#pragma unroll
        for (int h = 0; h < 2; h++) {
            const int i = er + h * 8;
            const int j = ec + nt * 8;
            float r0 = c[nt][h * 2 + 0] + wS[i * WP + j]     + bT[j * BP + i];
            float r1 = c[nt][h * 2 + 1] + wS[i * WP + j + 1] + bT[(j + 1) * BP + i];
            *reinterpret_cast<__half2*>(
                weffh + (size_t)(a * 64 + i) * KDIM + b * 64 + j) =
                __floats2half2_rn(r0, r1);
        }
    }
}

// ---------------- precompute 1b: x -> fp16 (RN) ----------------
__global__ void __launch_bounds__(256, 4)
bone_xcvt_kernel(const float* __restrict__ x, __half* __restrict__ xh) {
    size_t i = ((size_t)blockIdx.x * 256 + threadIdx.x) * 8;
    float4 v0 = *reinterpret_cast<const float4*>(x + i);
    float4 v1 = *reinterpret_cast<const float4*>(x + i + 4);
    __half2 h[4];
    h[0] = __floats2half2_rn(v0.x, v0.y);
    h[1] = __floats2half2_rn(v0.z, v0.w);
    h[2] = __floats2half2_rn(v1.x, v1.y);
    h[3] = __floats2half2_rn(v1.z, v1.w);
    *reinterpret_cast<uint4*>(xh + i) = *reinterpret_cast<uint4*>(h);
}

// ---------------- main GEMM kernel (fp16, byte-layout identical to proven R12) ----------------
__global__ void __launch_bounds__(THREADS, 2)
bone_gemm_kernel(const __half* __restrict__ xh, const __half* __restrict__ weffh,
                 float* __restrict__ out) {
    extern __shared__ __align__(128) char smem[];
    const uint32_t sb = smem_u32(smem);

    const int tid = threadIdx.x;
    const int wid = tid >> 5;
    const int lane = tid & 31;
    const int wm = wid & 1;        // 2 warps along M (64 rows each)
    const int wn = wid >> 1;       // 2 warps along N (64 cols each)
    const int bm = blockIdx.y * BM;
    const int bn = blockIdx.x * BN;

    // ---- cp.async: one quarter (2 A chunks + 2 B chunks per thread) ----
    // row = 64 halves = 128 B = 8 x 16B chunks (identical chunk map to R12)
    auto issue_part = [&](int kt, int stage, int part) {
        const uint32_t as = sb + stage * STAGE_BYTES;
        const uint32_t bs = as + A_STAGE_BYTES;
        const int kcol = kt * BK;   // halves
#pragma unroll
        for (int j = part * 2; j < part * 2 + 2; j++) {
            int idx = tid + j * THREADS;
            int row = idx >> 3, seg = idx & 7;
            cp16(as + row * PITCH_B + seg * 16,
                 xh + (size_t)(bm + row) * KDIM + kcol + seg * 8);
            cp16(bs + row * PITCH_B + seg * 16,
                 weffh + (size_t)(bn + row) * KDIM + kcol + seg * 8);
        }
    };

    float c[4][8][4];
#pragma unroll
    for (int mt = 0; mt < 4; mt++)
#pragma unroll
        for (int nt = 0; nt < 8; nt++)
#pragma unroll
            for (int q = 0; q < 4; q++) c[mt][nt][q] = 0.0f;

    // per-lane smem offsets (byte-identical to proven tf32 layout)
    const uint32_t a_row = (uint32_t)(wm * 64 + (lane & 15));
    const uint32_t a_coff = (uint32_t)((lane >> 4) * 16);          // k-half select (bytes)
    const uint32_t b_row = (uint32_t)(wn * 64 + (lane >> 2));      // + nt*8
    const uint32_t b_koff = (uint32_t)((lane & 3) * 4);            // k-pair (bytes)

    // double-buffered fragments
    uint32_t af[2][4][4];
    uint32_t bf[2][8][2];

    // one kstep = k16 = 32 bytes (same step as before)
    auto load_frags = [&](int stage, int ks, int buf) {
        const uint32_t as = sb + stage * STAGE_BYTES;
        const uint32_t bs = as + A_STAGE_BYTES;
        const uint32_t k0b = (uint32_t)(ks * 32);
#pragma unroll
        for (int mt = 0; mt < 4; mt++)
            ldmatrix4(af[buf][mt], as + (a_row + mt * 16) * PITCH_B + k0b + a_coff);
#pragma unroll
        for (int nt = 0; nt < 8; nt++) {
            uint32_t ba = bs + (b_row + nt * 8) * PITCH_B + k0b + b_koff;
            bf[buf][nt][0] = lds_b32(ba);
            bf[buf][nt][1] = lds_b32(ba + 16);
        }
    };

#define MMAS(B)                                                                    \
    do {                                                                           \
        _Pragma("unroll")                                                          \
        for (int mt = 0; mt < 4; mt++)                                             \
            _Pragma("unroll")                                                      \
            for (int nt = 0; nt < 8; nt++)                                         \
                mma_f16(c[mt][nt], af[B][mt], bf[B][nt]);                          \
    } while (0)

#define KT_BODY(KTV, CS, NS, F2, F3)                                               \
    do {                                                                           \
        const int _kt = (KTV);                                                     \
        const bool i23 = _kt + 2 < KT;                                             \
        const bool i3  = _kt + 3 < KT;                                             \
        load_frags(CS, 1, 1);                                                      \
        MMAS(0);                                                                   \
        if (i23) issue_part(_kt + 2, F2, 1);                                       \
        load_frags(CS, 2, 0);                                                      \
        MMAS(1);                                                                   \
        if (i23) issue_part(_kt + 2, F2, 2);                                       \
        load_frags(CS, 3, 1);                                                      \
        MMAS(0);                                                                   \
        if (i23) issue_part(_kt + 2, F2, 3);                                       \
        CP_COMMIT();                                                               \
        CP_WAIT1();                                                                \
        __syncthreads();                                                           \
        if (_kt + 1 < KT) load_frags(NS, 0, 0);                                    \
        MMAS(1);                                                                   \
        if (i3) issue_part(_kt + 3, F3, 0);                                        \
    } while (0)

    // ---- prologue: stage0 full, stage1 full, stage2 part0 ----
#pragma unroll
    for (int p = 0; p < 4; p++) issue_part(0, 0, p);
    CP_COMMIT();
#pragma unroll
    for (int p = 0; p < 4; p++) issue_part(1, 1, p);
    CP_COMMIT();
    issue_part(2, 2, 0);

    CP_WAIT1();          // stage0 group complete
    __syncthreads();
    load_frags(0, 0, 0); // frag0 of kt=0 into buf0

    // ---- mainloop: KT=64 -> 21 triples (kt = 0..62) + tail kt=63 (stage 0) ----
#pragma unroll 1
    for (int kt = 0; kt < 63; kt += 3) {
        KT_BODY(kt,     0, 1, 2, 0);
        KT_BODY(kt + 1, 1, 2, 0, 1);
        KT_BODY(kt + 2, 2, 0, 1, 2);
    }
    KT_BODY(63, 0, 1, 2, 0);

#undef KT_BODY
#undef MMAS

    // ---- epilogue: fp32 stores (c layout unchanged) ----
    const int er = bm + wm * 64 + (lane >> 2);
    const int ec = bn + wn * 64 + 2 * (lane & 3);
#pragma unroll
    for (int mt = 0; mt < 4; mt++) {
#pragma unroll
        for (int nt = 0; nt < 8; nt++) {
            float* p0 = out + (size_t)(er + mt * 16) * NDIM + ec + nt * 8;
            float* p1 = p0 + 8 * NDIM;
            *reinterpret_cast<float2*>(p0) = make_float2(c[mt][nt][0], c[mt][nt][1]);
            *reinterpret_cast<float2*>(p1) = make_float2(c[mt][nt][2], c[mt][nt][3]);
        }
    }
}

// ---------------- host ----------------
extern "C" void kernel_launch(void* const* d_in, const int* in_sizes, int n_in,
                              void* d_out, int out_size) {
    (void)in_sizes; (void)n_in; (void)out_size;
    const float* x      = (const float*)d_in[0];
    const float* weight = (const float*)d_in[1];
    const float* bone   = (const float*)d_in[2];
    float* out          = (float*)d_out;

    void* weffh_ptr = nullptr;
    cudaGetSymbolAddress(&weffh_ptr, g_weffh);
    void* xh_ptr = nullptr;
    cudaGetSymbolAddress(&xh_ptr, g_xh);

    cudaFuncSetAttribute((const void*)bone_gemm_kernel,
                         cudaFuncAttributeMaxDynamicSharedMemorySize, SMEM_TOTAL);

    bone_weff_kernel<<<dim3(64, 64), 128>>>(weight, bone, (__half*)weffh_ptr);
    bone_xcvt_kernel<<<(int)(((size_t)MDIM * KDIM) / (256 * 8)), 256>>>(x, (__half*)xh_ptr);
    bone_gemm_kernel<<<dim3(NDIM / BN, MDIM / BM), THREADS, SMEM_TOTAL>>>(
        (const __half*)xh_ptr, (const __half*)weffh_ptr, out);
}